// round 8
// baseline (speedup 1.0000x reference)
#include <cuda_runtime.h>
#include <cuda_bf16.h>

// Fused 13-tap depthwise conv (FD-5 composed with Gauss-9).
//   z[t] = sum_{k=0..12} w[k] * x[t+k]
// x [8,4,1048576] fp32 -> out [8,4,1048564] fp32 (32 independent rows).
//
// R8: residual-latency fixes.
//  - w is symmetric (conv of two symmetric kernels): only 7 unique weights.
//    Stencil computed as w6*a[m] + sum w[k]*(a[k]+a[12-k]) -> frees ~6 regs.
//  - __launch_bounds__(256,7): cap ~36 regs -> 7 CTAs/SM (56 warps).
//  - Branch-free halo patches: clamped addresses + independent predicated
//    loads (L1-hit: data == next chunk's primary, fetched in phase 1).
//  - Primary LDGs issued BEFORE the weight-smem __syncthreads so the
//    barrier hides under DRAM latency.

#define T_IN 1048576
#define G_IN 262144              // float4 groups per input row
#define G_OUT 262141             // float4 groups per output row (1048564/4)
#define N_ROWS 32
#define WARPS_PER_BLOCK 8
#define CHUNKS_PER_WARP 4
#define BLOCKS_X 256             // 256*8*4 = 8192 chunks = ceil(262141/32)

__device__ __forceinline__ float4 shfl_down_f4(float4 v, int delta) {
    float4 r;
    r.x = __shfl_down_sync(0xffffffffu, v.x, delta);
    r.y = __shfl_down_sync(0xffffffffu, v.y, delta);
    r.z = __shfl_down_sync(0xffffffffu, v.z, delta);
    r.w = __shfl_down_sync(0xffffffffu, v.w, delta);
    return r;
}

__global__ __launch_bounds__(256, 7)
void fused_conv13_kernel(const float* __restrict__ x,
                         float4* __restrict__ out,
                         const float* __restrict__ fd,
                         const float* __restrict__ gs) {
    __shared__ float ws[7];

    const int warp = threadIdx.x >> 5;
    const int lane = threadIdx.x & 31;
    const int row  = blockIdx.y;

    // Composite symmetric weights: w[k] = sum_i fd[i]*gauss[k-i], k=0..6
    // (w[12-k] == w[k], both source kernels symmetric).
    if (threadIdx.x < 7) {
        int k = threadIdx.x;
        float s = 0.0f;
        #pragma unroll
        for (int i = 0; i < 5; i++) {
            int j = k - i;
            if (j >= 0 && j < 9) s += fd[i] * gs[j];
        }
        ws[k] = s;
    }

    const float4* __restrict__ in4 = (const float4*)(x + (size_t)row * T_IN);
    float4* __restrict__ out4 = out + (size_t)row * G_OUT;

    const int chunk0 = (blockIdx.x * WARPS_PER_BLOCK + warp) * CHUNKS_PER_WARP;
    const int gl0 = (chunk0 << 5) + lane;

    // ---- Phase 1: batch all primary loads (MLP = 4), before the barrier ----
    float4 v0[CHUNKS_PER_WARP];
    #pragma unroll
    for (int i = 0; i < CHUNKS_PER_WARP; i++) {
        v0[i] = in4[gl0 + (i << 5)];      // <= 262143, always in-bounds
    }

    __syncthreads();                       // hides under the DRAM latency above

    float w0 = ws[0], w1 = ws[1], w2 = ws[2], w3 = ws[3],
          w4 = ws[4], w5 = ws[5], w6 = ws[6];

    // ---- Phase 2: per-chunk halo + FMA + store ----
    #pragma unroll
    for (int i = 0; i < CHUNKS_PER_WARP; i++) {
        const int g = gl0 + (i << 5);

        float4 v1 = shfl_down_f4(v0[i], 1);
        float4 v2 = shfl_down_f4(v0[i], 2);
        float4 v3 = shfl_down_f4(v0[i], 3);

        // Branch-free edge patches (clamped addresses; L1-hit — same lines
        // as the next chunk's phase-1 primaries). Garbage only feeds
        // outputs with g >= G_OUT, which are never stored.
        const int m1 = min(g + 1, G_IN - 1);
        const int m2 = min(g + 2, G_IN - 1);
        const int m3 = min(g + 3, G_IN - 1);
        if (lane >= 29) v3 = in4[m3];
        if (lane >= 30) v2 = in4[m2];
        if (lane == 31) v1 = in4[m1];

        const float a0=v0[i].x, a1=v0[i].y, a2=v0[i].z, a3=v0[i].w;
        const float a4=v1.x,  a5=v1.y,  a6=v1.z,  a7=v1.w;
        const float a8=v2.x,  a9=v2.y,  a10=v2.z, a11=v2.w;
        const float a12=v3.x, a13=v3.y, a14=v3.z, a15=v3.w;

        // Symmetric stencil: r = w6*center + sum_{k=0..5} w[k]*(left+right)
        float r0 = w6 * a6;
        r0 = fmaf(w0, a0 + a12, r0);
        r0 = fmaf(w1, a1 + a11, r0);
        r0 = fmaf(w2, a2 + a10, r0);
        r0 = fmaf(w3, a3 + a9,  r0);
        r0 = fmaf(w4, a4 + a8,  r0);
        r0 = fmaf(w5, a5 + a7,  r0);

        float r1 = w6 * a7;
        r1 = fmaf(w0, a1 + a13, r1);
        r1 = fmaf(w1, a2 + a12, r1);
        r1 = fmaf(w2, a3 + a11, r1);
        r1 = fmaf(w3, a4 + a10, r1);
        r1 = fmaf(w4, a5 + a9,  r1);
        r1 = fmaf(w5, a6 + a8,  r1);

        float r2 = w6 * a8;
        r2 = fmaf(w0, a2 + a14, r2);
        r2 = fmaf(w1, a3 + a13, r2);
        r2 = fmaf(w2, a4 + a12, r2);
        r2 = fmaf(w3, a5 + a11, r2);
        r2 = fmaf(w4, a6 + a10, r2);
        r2 = fmaf(w5, a7 + a9,  r2);

        float r3 = w6 * a9;
        r3 = fmaf(w0, a3 + a15, r3);
        r3 = fmaf(w1, a4 + a14, r3);
        r3 = fmaf(w2, a5 + a13, r3);
        r3 = fmaf(w3, a6 + a12, r3);
        r3 = fmaf(w4, a7 + a11, r3);
        r3 = fmaf(w5, a8 + a10, r3);

        float4 o; o.x = r0; o.y = r1; o.z = r2; o.w = r3;
        if (g < G_OUT) out4[g] = o;        // predicated; false only in row tail
    }
}

extern "C" void kernel_launch(void* const* d_in, const int* in_sizes, int n_in,
                              void* d_out, int out_size) {
    const float* x  = (const float*)d_in[0];   // [8,4,1048576]
    const float* fd = (const float*)d_in[1];   // [5]
    const float* gs = (const float*)d_in[2];   // [9]
    float4* out = (float4*)d_out;              // [8,4,1048564] as float4 groups

    dim3 grid(BLOCKS_X, N_ROWS);
    fused_conv13_kernel<<<grid, 256>>>(x, out, fd, gs);
}

// round 10
// speedup vs baseline: 1.0085x; 1.0085x over previous
#include <cuda_runtime.h>
#include <cuda_bf16.h>

// Fused 13-tap depthwise conv (FD-5 composed with Gauss-9).
//   z[t] = sum_{k=0..12} w[k] * x[t+k]
// x [8,4,1048576] fp32 -> out [8,4,1048564] fp32 (32 independent rows).
//
// R9: R7 structure (no reg cap, nested-if edge patches) + deeper MLP.
//  - CHUNKS_PER_WARP 4 -> 8: phase 1 issues 8 back-to-back LDG.128 per
//    thread (32 regs in flight). MLP-per-warp doubles; occupancy drops to
//    ~4 CTAs/SM, which the R8 experiment showed is the right trade
//    (R8: +occ/-MLP regressed).
//  - Symmetric composite weights (w[k]==w[12-k], both source kernels
//    symmetric): 7 weight regs, 6 FADD + 7 FMA per output (13 flop, same).
//  - Primary loads issue before the weight-smem __syncthreads.

#define T_IN 1048576
#define G_IN 262144              // float4 groups per input row
#define G_OUT 262141             // float4 groups per output row (1048564/4)
#define N_ROWS 32
#define WARPS_PER_BLOCK 8
#define CHUNKS_PER_WARP 8
#define BLOCKS_X 128             // 128*8*8 = 8192 chunks = ceil(262141/32)

__device__ __forceinline__ float4 shfl_down_f4(float4 v, int delta) {
    float4 r;
    r.x = __shfl_down_sync(0xffffffffu, v.x, delta);
    r.y = __shfl_down_sync(0xffffffffu, v.y, delta);
    r.z = __shfl_down_sync(0xffffffffu, v.z, delta);
    r.w = __shfl_down_sync(0xffffffffu, v.w, delta);
    return r;
}

__global__ __launch_bounds__(256)
void fused_conv13_kernel(const float* __restrict__ x,
                         float4* __restrict__ out,
                         const float* __restrict__ fd,
                         const float* __restrict__ gs) {
    __shared__ float ws[7];

    const int warp = threadIdx.x >> 5;
    const int lane = threadIdx.x & 31;
    const int row  = blockIdx.y;

    // Composite symmetric weights: w[k] = sum_i fd[i]*gauss[k-i], k=0..6.
    if (threadIdx.x < 7) {
        int k = threadIdx.x;
        float s = 0.0f;
        #pragma unroll
        for (int i = 0; i < 5; i++) {
            int j = k - i;
            if (j >= 0 && j < 9) s += fd[i] * gs[j];
        }
        ws[k] = s;
    }

    const float4* __restrict__ in4 = (const float4*)(x + (size_t)row * T_IN);
    float4* __restrict__ out4 = out + (size_t)row * G_OUT;

    const int chunk0 = (blockIdx.x * WARPS_PER_BLOCK + warp) * CHUNKS_PER_WARP;
    const int gl0 = (chunk0 << 5) + lane;

    // ---- Phase 1: batch ALL primary loads back-to-back (MLP = 8) ----
    float4 v0[CHUNKS_PER_WARP];
    #pragma unroll
    for (int i = 0; i < CHUNKS_PER_WARP; i++) {
        v0[i] = in4[gl0 + (i << 5)];      // g <= 262143, always in-bounds
    }

    __syncthreads();                       // hides under DRAM latency above

    const float w0 = ws[0], w1 = ws[1], w2 = ws[2], w3 = ws[3],
                w4 = ws[4], w5 = ws[5], w6 = ws[6];

    // ---- Phase 2: per-chunk halo + FMA + store ----
    #pragma unroll
    for (int i = 0; i < CHUNKS_PER_WARP; i++) {
        const int g0 = gl0 - lane + (i << 5);
        const int g  = g0 + lane;
        const bool fast = (g0 + 35) <= G_IN;   // only the global last chunk is slow

        float4 v1 = shfl_down_f4(v0[i], 1);
        float4 v2 = shfl_down_f4(v0[i], 2);
        float4 v3 = shfl_down_f4(v0[i], 3);

        if (fast) {
            // Edge-lane patches: L1-hot (same lines as a neighboring warp's
            // phase-1 primaries).
            if (lane >= 29) {
                v3 = in4[g + 3];
                if (lane >= 30) v2 = in4[g + 2];
                if (lane == 31) v1 = in4[g + 1];
            }
        }
        // slow chunk (row tail): lanes 29-31 hold garbage halo but their
        // outputs (g >= G_OUT) are never stored.

        const float a0=v0[i].x, a1=v0[i].y, a2=v0[i].z, a3=v0[i].w;
        const float a4=v1.x,  a5=v1.y,  a6=v1.z,  a7=v1.w;
        const float a8=v2.x,  a9=v2.y,  a10=v2.z, a11=v2.w;
        const float a12=v3.x, a13=v3.y, a14=v3.z, a15=v3.w;

        // Symmetric stencil: r = w6*center + sum_{k=0..5} w[k]*(left+right)
        float r0 = w6 * a6;
        r0 = fmaf(w0, a0 + a12, r0);
        r0 = fmaf(w1, a1 + a11, r0);
        r0 = fmaf(w2, a2 + a10, r0);
        r0 = fmaf(w3, a3 + a9,  r0);
        r0 = fmaf(w4, a4 + a8,  r0);
        r0 = fmaf(w5, a5 + a7,  r0);

        float r1 = w6 * a7;
        r1 = fmaf(w0, a1 + a13, r1);
        r1 = fmaf(w1, a2 + a12, r1);
        r1 = fmaf(w2, a3 + a11, r1);
        r1 = fmaf(w3, a4 + a10, r1);
        r1 = fmaf(w4, a5 + a9,  r1);
        r1 = fmaf(w5, a6 + a8,  r1);

        float r2 = w6 * a8;
        r2 = fmaf(w0, a2 + a14, r2);
        r2 = fmaf(w1, a3 + a13, r2);
        r2 = fmaf(w2, a4 + a12, r2);
        r2 = fmaf(w3, a5 + a11, r2);
        r2 = fmaf(w4, a6 + a10, r2);
        r2 = fmaf(w5, a7 + a9,  r2);

        float r3 = w6 * a9;
        r3 = fmaf(w0, a3 + a15, r3);
        r3 = fmaf(w1, a4 + a14, r3);
        r3 = fmaf(w2, a5 + a13, r3);
        r3 = fmaf(w3, a6 + a12, r3);
        r3 = fmaf(w4, a7 + a11, r3);
        r3 = fmaf(w5, a8 + a10, r3);

        float4 o; o.x = r0; o.y = r1; o.z = r2; o.w = r3;
        if (fast) {
            out4[g] = o;
        } else if (g < G_OUT) {
            out4[g] = o;
        }
    }
}

extern "C" void kernel_launch(void* const* d_in, const int* in_sizes, int n_in,
                              void* d_out, int out_size) {
    const float* x  = (const float*)d_in[0];   // [8,4,1048576]
    const float* fd = (const float*)d_in[1];   // [5]
    const float* gs = (const float*)d_in[2];   // [9]
    float4* out = (float4*)d_out;              // [8,4,1048564] as float4 groups

    dim3 grid(BLOCKS_X, N_ROWS);
    fused_conv13_kernel<<<grid, 256>>>(x, out, fd, gs);
}